// round 2
// baseline (speedup 1.0000x reference)
#include <cuda_runtime.h>
#include <cstdint>

// Problem constants
#define NB   8
#define SQL  2048
#define SKL  2048
#define HIDN 1024
// NORM = sqrt(1024) = 32  -> alpha = 1/32

// Scratch (allocation-free rule: __device__ globals)
__device__ float g_q [(size_t)NB * SQL * HIDN];   // 64 MiB
__device__ float g_k [(size_t)NB * SKL * HIDN];   // 64 MiB
__device__ float g_vt[(size_t)NB * HIDN * SKL];   // 64 MiB  (V transposed per batch: [b][h][sk])

// ---------------------------------------------------------------------------
// TF32 helpers
// ---------------------------------------------------------------------------
__device__ __forceinline__ float to_tf32(float x) {
    unsigned u;
    asm("cvt.rna.tf32.f32 %0, %1;" : "=r"(u) : "f"(x));
    return __uint_as_float(u);
}

__device__ __forceinline__ void mma8(float* c, const unsigned* a, unsigned b0, unsigned b1) {
    asm volatile(
        "mma.sync.aligned.m16n8k8.row.col.f32.tf32.tf32.f32 "
        "{%0,%1,%2,%3}, {%4,%5,%6,%7}, {%8,%9}, {%0,%1,%2,%3};\n"
        : "+f"(c[0]), "+f"(c[1]), "+f"(c[2]), "+f"(c[3])
        : "r"(a[0]), "r"(a[1]), "r"(a[2]), "r"(a[3]), "r"(b0), "r"(b1));
}

// ---------------------------------------------------------------------------
// Generic NT GEMM:  C[m,n] = sum_k A[m,k] * B[n,k]   (+epilogue)
//   MODE 0: C = acc + bias[n]                 (row-major store)
//   MODE 1: Vt store: out[b][n][sk] = acc + bias[n]   (b = m>>11, sk = m&2047)
//   MODE 2: C = acc/32, mask==0 -> -inf       (row-major store)
//   MODE 3: C = acc                           (row-major store)
// Tiles: BM=BN=128, BK=16.  256 threads, 8 warps (4 x 2), warp tile 32x64.
// Requires M%128==0, N%128==0, K%16==0 (all shapes here satisfy this).
// ---------------------------------------------------------------------------
template<int MODE>
__launch_bounds__(256)
__global__ void gemm_nt(const float* __restrict__ Ag, const float* __restrict__ Bg,
                        const float* __restrict__ bias, const int* __restrict__ mask,
                        float* __restrict__ Cg,
                        int M, int N, int K,
                        long sA, long sB, long sC, long sM)
{
    constexpr int BM = 128, BN = 128, BK = 16, LD = 20;  // LD pad -> conflict-free frags
    __shared__ float As[2][BM][LD];
    __shared__ float Bs[2][BN][LD];

    const int bz = blockIdx.z;
    Ag += (long)bz * sA;
    Bg += (long)bz * sB;
    if (MODE != 1) Cg += (long)bz * sC;
    if (MODE == 2) mask += (long)bz * sM;

    const int m0 = blockIdx.y * BM;
    const int n0 = blockIdx.x * BN;
    const int t    = threadIdx.x;
    const int lane = t & 31, warp = t >> 5;
    const int wm = (warp & 3) * 32;   // warp m-offset within block
    const int wn = (warp >> 2) * 64;  // warp n-offset within block
    const int g  = lane >> 2;         // groupID 0..7
    const int tg = lane & 3;          // thread-in-group 0..3

    // global staging: each thread loads 2 float4 of A and 2 of B per k-tile
    const int lr0 = t >> 2;           // 0..63
    const int lc  = (t & 3) * 4;      // 0,4,8,12
    const float* Aptr0 = Ag + (long)(m0 + lr0)      * K + lc;
    const float* Aptr1 = Ag + (long)(m0 + lr0 + 64) * K + lc;
    const float* Bptr0 = Bg + (long)(n0 + lr0)      * K + lc;
    const float* Bptr1 = Bg + (long)(n0 + lr0 + 64) * K + lc;

    float acc[2][8][4];
    #pragma unroll
    for (int i = 0; i < 2; i++)
        #pragma unroll
        for (int j = 0; j < 8; j++)
            #pragma unroll
            for (int l = 0; l < 4; l++) acc[i][j][l] = 0.f;

    float4 a0r, a1r, b0r, b1r;

    auto ldg = [&](int kt) {
        const long o = (long)kt * BK;
        a0r = *(const float4*)(Aptr0 + o);
        a1r = *(const float4*)(Aptr1 + o);
        b0r = *(const float4*)(Bptr0 + o);
        b1r = *(const float4*)(Bptr1 + o);
    };
    auto sts = [&](int buf) {
        As[buf][lr0     ][lc + 0] = to_tf32(a0r.x);
        As[buf][lr0     ][lc + 1] = to_tf32(a0r.y);
        As[buf][lr0     ][lc + 2] = to_tf32(a0r.z);
        As[buf][lr0     ][lc + 3] = to_tf32(a0r.w);
        As[buf][lr0 + 64][lc + 0] = to_tf32(a1r.x);
        As[buf][lr0 + 64][lc + 1] = to_tf32(a1r.y);
        As[buf][lr0 + 64][lc + 2] = to_tf32(a1r.z);
        As[buf][lr0 + 64][lc + 3] = to_tf32(a1r.w);
        Bs[buf][lr0     ][lc + 0] = to_tf32(b0r.x);
        Bs[buf][lr0     ][lc + 1] = to_tf32(b0r.y);
        Bs[buf][lr0     ][lc + 2] = to_tf32(b0r.z);
        Bs[buf][lr0     ][lc + 3] = to_tf32(b0r.w);
        Bs[buf][lr0 + 64][lc + 0] = to_tf32(b1r.x);
        Bs[buf][lr0 + 64][lc + 1] = to_tf32(b1r.y);
        Bs[buf][lr0 + 64][lc + 2] = to_tf32(b1r.z);
        Bs[buf][lr0 + 64][lc + 3] = to_tf32(b1r.w);
    };
    auto comp = [&](int buf) {
        #pragma unroll
        for (int ks = 0; ks < 2; ks++) {
            const int k0 = ks * 8;
            unsigned af[2][4];
            #pragma unroll
            for (int mt = 0; mt < 2; mt++) {
                const int r = wm + mt * 16 + g;
                af[mt][0] = __float_as_uint(As[buf][r    ][k0 + tg    ]);
                af[mt][1] = __float_as_uint(As[buf][r + 8][k0 + tg    ]);
                af[mt][2] = __float_as_uint(As[buf][r    ][k0 + tg + 4]);
                af[mt][3] = __float_as_uint(As[buf][r + 8][k0 + tg + 4]);
            }
            #pragma unroll
            for (int nt = 0; nt < 8; nt++) {
                const int rn = wn + nt * 8 + g;
                const unsigned bf0 = __float_as_uint(Bs[buf][rn][k0 + tg    ]);
                const unsigned bf1 = __float_as_uint(Bs[buf][rn][k0 + tg + 4]);
                mma8(acc[0][nt], af[0], bf0, bf1);
                mma8(acc[1][nt], af[1], bf0, bf1);
            }
        }
    };

    // mainloop, double buffered
    ldg(0); sts(0); __syncthreads();
    const int nK = K / BK;
    for (int kt = 0; kt < nK; kt++) {
        const int cur = kt & 1;
        if (kt + 1 < nK) ldg(kt + 1);
        comp(cur);
        if (kt + 1 < nK) sts(cur ^ 1);
        __syncthreads();
    }

    // epilogue
    const float NEG = __int_as_float(0xff800000);  // -inf
    #pragma unroll
    for (int mt = 0; mt < 2; mt++) {
        #pragma unroll
        for (int nt = 0; nt < 8; nt++) {
            const int row = m0 + wm + mt * 16 + g;
            const int col = n0 + wn + nt * 8 + tg * 2;
            float* c = acc[mt][nt];
            if (MODE == 0) {
                const float bb0 = bias[col], bb1 = bias[col + 1];
                float2 v0 = make_float2(c[0] + bb0, c[1] + bb1);
                float2 v1 = make_float2(c[2] + bb0, c[3] + bb1);
                *(float2*)&Cg[(long)row       * N + col] = v0;
                *(float2*)&Cg[(long)(row + 8) * N + col] = v1;
            } else if (MODE == 1) {
                const float bb0 = bias[col], bb1 = bias[col + 1];
                const int b_ = row >> 11, sk = row & 2047;
                const long i00 = ((long)b_ * N + col) * 2048 + sk;  // out[b][col][sk]
                Cg[i00             ] = c[0] + bb0;
                Cg[i00 + 2048     ] = c[1] + bb1;   // col+1
                Cg[i00 + 8        ] = c[2] + bb0;   // sk+8
                Cg[i00 + 2048 + 8 ] = c[3] + bb1;
            } else if (MODE == 2) {
                const long r0 = (long)row * N + col;
                const long r1 = (long)(row + 8) * N + col;
                const int m00 = mask[r0], m01 = mask[r0 + 1];
                const int m10 = mask[r1], m11 = mask[r1 + 1];
                const float sc = 0.03125f;  // 1/32
                float2 v0 = make_float2(m00 ? c[0] * sc : NEG, m01 ? c[1] * sc : NEG);
                float2 v1 = make_float2(m10 ? c[2] * sc : NEG, m11 ? c[3] * sc : NEG);
                *(float2*)&Cg[r0] = v0;
                *(float2*)&Cg[r1] = v1;
            } else {
                float2 v0 = make_float2(c[0], c[1]);
                float2 v1 = make_float2(c[2], c[3]);
                *(float2*)&Cg[(long)row       * N + col] = v0;
                *(float2*)&Cg[(long)(row + 8) * N + col] = v1;
            }
        }
    }
}

// ---------------------------------------------------------------------------
// Row softmax over SK=2048 with -inf masking; fully-masked row -> all zeros
// (matches reference's softmax + isnan cleanup). One block per row, 256 thr.
// ---------------------------------------------------------------------------
__device__ __forceinline__ float warpRedMax(float v) {
    #pragma unroll
    for (int o = 16; o > 0; o >>= 1) v = fmaxf(v, __shfl_xor_sync(0xffffffffu, v, o));
    return v;
}
__device__ __forceinline__ float warpRedSum(float v) {
    #pragma unroll
    for (int o = 16; o > 0; o >>= 1) v += __shfl_xor_sync(0xffffffffu, v, o);
    return v;
}

__global__ void softmax_k(float* __restrict__ S) {
    const long row = blockIdx.x;
    float4* p4 = (float4*)(S + row * (long)SKL);
    const int t = threadIdx.x;
    __shared__ float red[8];

    float4 v0 = p4[t], v1 = p4[t + 256];
    float m = fmaxf(fmaxf(fmaxf(v0.x, v0.y), fmaxf(v0.z, v0.w)),
                    fmaxf(fmaxf(v1.x, v1.y), fmaxf(v1.z, v1.w)));
    m = warpRedMax(m);
    if ((t & 31) == 0) red[t >> 5] = m;
    __syncthreads();
    m = red[0];
    #pragma unroll
    for (int i = 1; i < 8; i++) m = fmaxf(m, red[i]);
    __syncthreads();

    if (m == __int_as_float(0xff800000)) {   // fully masked row -> zeros
        float4 z = make_float4(0.f, 0.f, 0.f, 0.f);
        p4[t] = z; p4[t + 256] = z;
        return;
    }

    v0.x = __expf(v0.x - m); v0.y = __expf(v0.y - m);
    v0.z = __expf(v0.z - m); v0.w = __expf(v0.w - m);
    v1.x = __expf(v1.x - m); v1.y = __expf(v1.y - m);
    v1.z = __expf(v1.z - m); v1.w = __expf(v1.w - m);

    float s = v0.x + v0.y + v0.z + v0.w + v1.x + v1.y + v1.z + v1.w;
    s = warpRedSum(s);
    if ((t & 31) == 0) red[t >> 5] = s;
    __syncthreads();
    s = red[0];
    #pragma unroll
    for (int i = 1; i < 8; i++) s += red[i];

    const float inv = 1.0f / s;
    v0.x *= inv; v0.y *= inv; v0.z *= inv; v0.w *= inv;
    v1.x *= inv; v1.y *= inv; v1.z *= inv; v1.w *= inv;
    p4[t] = v0; p4[t + 256] = v1;
}

// ---------------------------------------------------------------------------
// kernel_launch
// inputs: 0 key, 1 query, 2 mask, 3 Wq, 4 bq, 5 Wk, 6 bk, 7 Wv, 8 bv
// output: [output (B,SQ,H) fp32 | score (B,SQ,SK) fp32]
// ---------------------------------------------------------------------------
extern "C" void kernel_launch(void* const* d_in, const int* in_sizes, int n_in,
                              void* d_out, int out_size)
{
    const float* key   = (const float*)d_in[0];
    const float* query = (const float*)d_in[1];
    const int*   mask  = (const int*)  d_in[2];
    const float* Wq    = (const float*)d_in[3];
    const float* bq    = (const float*)d_in[4];
    const float* Wk    = (const float*)d_in[5];
    const float* bk    = (const float*)d_in[6];
    const float* Wv    = (const float*)d_in[7];
    const float* bv    = (const float*)d_in[8];

    float* out   = (float*)d_out;
    float* score = out + (long)NB * SQL * HIDN;

    float *q, *k, *vt;
    cudaGetSymbolAddress((void**)&q,  g_q);
    cudaGetSymbolAddress((void**)&k,  g_k);
    cudaGetSymbolAddress((void**)&vt, g_vt);

    dim3 blk(256);

    // QKV projections: M=16384, N=1024, K=1024  (NT: y = x @ W^T + b)
    dim3 gp(HIDN / 128, (NB * SQL) / 128, 1);
    gemm_nt<0><<<gp, blk>>>(query, Wq, bq, nullptr, q,  NB * SQL, HIDN, HIDN, 0, 0, 0, 0);
    gemm_nt<0><<<gp, blk>>>(key,   Wk, bk, nullptr, k,  NB * SKL, HIDN, HIDN, 0, 0, 0, 0);
    gemm_nt<1><<<gp, blk>>>(key,   Wv, bv, nullptr, vt, NB * SKL, HIDN, HIDN, 0, 0, 0, 0);

    // Scores: per batch  S = (Q K^T)/32 with mask -> -inf
    dim3 gs(SKL / 128, SQL / 128, NB);
    gemm_nt<2><<<gs, blk>>>(q, k, nullptr, mask, score, SQL, SKL, HIDN,
                            (long)SQL * HIDN, (long)SKL * HIDN,
                            (long)SQL * SKL,  (long)SQL * SKL);

    // Row softmax (in place on the score output region)
    softmax_k<<<NB * SQL, 256>>>(score);

    // Output: per batch  O = P @ V  == P (NT) Vt
    dim3 go(HIDN / 128, SQL / 128, NB);
    gemm_nt<3><<<go, blk>>>(score, vt, nullptr, nullptr, out, SQL, HIDN, SKL,
                            (long)SQL * SKL, (long)HIDN * SKL,
                            (long)SQL * HIDN, 0);
}